// round 11
// baseline (speedup 1.0000x reference)
#include <cuda_runtime.h>
#include <math.h>

// Problem constants
#define NN     512
#define HID    1024
#define OUTD   131328          // N + N*(N-1)/2
#define OUT4   (OUTD / 4)      // 32832 float4 columns
#define SPLITK 8
#define JCH    (HID / SPLITK)  // 128 rows of Wo per k-chunk
#define SI     32              // i-splits in fused MLP head
#define FB     1032            // blocks in fused mlp+gemv kernel (129 x 8)
#define GT     136             // lower-triangle 32x32 tiles (16*17/2)

// Device scratch (no allocation allowed). Referenced ONLY in device code.
// Partials stored [j][SI] so consumers reduce with contiguous float4 loads.
__device__ float g_hp[3][HID][SI];
__device__ float g_part[SPLITK][OUTD];   // split-K partial sums of big GEMV
__device__ float g_L[NN * NN];

// ---------------------------------------------------------------------------
// Software grid barrier (sense-reversal). Safe when all participating blocks
// are co-resident (FB=1032 at 7 CTAs/SM = 1036 slots; GT=136 <= 148).
// Generation is monotonic across kernels and graph replays.
// ---------------------------------------------------------------------------
__device__ unsigned g_bar_ctr = 0;
__device__ volatile unsigned g_bar_gen = 0;

__device__ __forceinline__ void grid_barrier(unsigned nblocks) {
    __threadfence();
    __syncthreads();
    if (threadIdx.x == 0) {
        unsigned gen = g_bar_gen;
        if (atomicAdd(&g_bar_ctr, 1) == nblocks - 1) {
            g_bar_ctr = 0;
            __threadfence();
            g_bar_gen = gen + 1;
        } else {
            while (g_bar_gen == gen) __nanosleep(32);
        }
        __threadfence();
    }
    __syncthreads();
}

// ---------------------------------------------------------------------------
// MLP partial for the fused head. Block (cg, isp): for the 32 columns
// j = cg*32 + lane, accumulate over isp's i-slice (CHUNK = IN/SI rows).
// Warp lanes -> 32 consecutive columns: one 128B line per W row.
// ---------------------------------------------------------------------------
template <int IN>
__device__ __forceinline__ void mlp_partial(
    const float* __restrict__ xs, const float* __restrict__ W,
    int cg, int isp, int layer, float sh[8][32]) {
    const int CHUNK = IN / SI;
    const int CH    = CHUNK / 8;
    const int lane  = threadIdx.x & 31;
    const int w     = threadIdx.x >> 5;
    const int j     = cg * 32 + lane;
    const int base  = isp * CHUNK;
    const int i0    = w * CH;

    float acc = 0.f;
#pragma unroll
    for (int i = 0; i < CH; ++i) {
        acc += xs[i0 + i] * __ldg(&W[(size_t)(base + i0 + i) * 1024 + j]);
    }
    sh[w][lane] = acc;
    __syncthreads();
    if (w == 0) {
        float s = 0.f;
#pragma unroll
        for (int q = 0; q < 8; ++q) s += sh[q][lane];
        g_hp[layer][j][isp] = s;
    }
    __syncthreads();
}

// Reduce SI=32 partials for element g: 8 contiguous float4 loads.
__device__ __forceinline__ float reduce_partials(int layer, int g) {
    const float4* p = (const float4*)g_hp[layer][g];
    float s = 0.f;
#pragma unroll
    for (int q = 0; q < 8; ++q) {
        float4 v = p[q];
        s += (v.x + v.y) + (v.z + v.w);
    }
    return s;
}

// ---------------------------------------------------------------------------
// Fused MLP + big GEMV. grid = 1032, block = 256, 7 CTAs/SM.
// Head: 3 MLP layers across blocks 0..1023 (32 colgroups x SI=32 i-splits),
// grid barriers between layers (cheap: phases are ~0.5us, minimal spread).
// Tail: the proven split-K gemv (86% DRAM), h2 finalized at staging.
// ---------------------------------------------------------------------------
__global__ void __launch_bounds__(256, 7)
mlp_gemv(const float* __restrict__ x,
         const float* __restrict__ W0, const float* __restrict__ b0,
         const float* __restrict__ W1, const float* __restrict__ b1,
         const float* __restrict__ W2, const float* __restrict__ b2,
         const float* __restrict__ Wo) {
    __shared__ float sh[8][32];
    __shared__ float xs[HID / SI];
    __shared__ float hs[JCH];

    const int b  = blockIdx.x;
    const int t  = threadIdx.x;
    const int cg  = b & 31;
    const int isp = b >> 5;
    const bool active = (b < 1024);

    // ---- layer 0: IN=512, raw input ----
    if (active) {
        const int CHUNK = 512 / SI;   // 16
        if (t < CHUNK) xs[t] = x[isp * CHUNK + t];
        __syncthreads();
        mlp_partial<512>(xs, W0, cg, isp, 0, sh);
    }
    grid_barrier(FB);

    // ---- layer 1: IN=1024 ----
    if (active) {
        const int CHUNK = HID / SI;   // 32
        if (t < CHUNK) {
            const int g = isp * CHUNK + t;
            xs[t] = tanhf(reduce_partials(0, g) + __ldg(&b0[g]));
        }
        __syncthreads();
        mlp_partial<1024>(xs, W1, cg, isp, 1, sh);
    }
    grid_barrier(FB);

    // ---- layer 2: IN=1024 ----
    if (active) {
        const int CHUNK = HID / SI;
        if (t < CHUNK) {
            const int g = isp * CHUNK + t;
            xs[t] = tanhf(reduce_partials(1, g) + __ldg(&b1[g]));
        }
        __syncthreads();
        mlp_partial<1024>(xs, W2, cg, isp, 2, sh);
    }
    grid_barrier(FB);

    // ---- big GEMV (split-K), identical core to the 79.4us version ----
    {
        const int chunk = b & 7;       // 0..7
        const int kb    = b >> 3;      // 0..128
        if (t < JCH) {
            const int g = chunk * JCH + t;
            hs[t] = tanhf(reduce_partials(2, g) + __ldg(&b2[g]));
        }
        __syncthreads();

        const int k4 = kb * 256 + t;
        if (k4 < OUT4) {
            const float4* W4 = (const float4*)Wo + (size_t)chunk * JCH * OUT4;
            float ax = 0.f, ay = 0.f, az = 0.f, aw = 0.f;
#pragma unroll 8
            for (int j = 0; j < JCH; ++j) {
                float4 wv = __ldcs(&W4[(size_t)j * OUT4 + k4]);
                float  hj = hs[j];
                ax += hj * wv.x;
                ay += hj * wv.y;
                az += hj * wv.z;
                aw += hj * wv.w;
            }
            float4 r; r.x = ax; r.y = ay; r.z = az; r.w = aw;
            ((float4*)g_part[chunk])[k4] = r;
        }
    }
}

// ---------------------------------------------------------------------------
// Fused build_L + D = L*L^T. grid = GT=136 blocks (lower-triangle tiles),
// block = 256. Phase A: grid-stride build L. Barrier(136). Phase B: GEMM,
// triangular-k, 4x4 microtiles, 4-way k-split, smem-overlaid reduction.
// ---------------------------------------------------------------------------
__global__ void __launch_bounds__(256)
buildL_gemm(const float* __restrict__ bo, float* __restrict__ D) {
    __shared__ float SAB[2][64][36];   // As/Bs; reduction buffer overlaid

    const int b = blockIdx.x;
    const int t = threadIdx.x;

    // linear block id -> (bi, bj), bj <= bi
    int bi = (int)((sqrtf(8.f * b + 1.f) - 1.f) * 0.5f);
    while ((bi + 1) * (bi + 2) / 2 <= b) ++bi;
    while (bi * (bi + 1) / 2 > b) --bi;
    const int bj = b - bi * (bi + 1) / 2;

    // ---- Phase A: build L ----
    {
        const int T = GT * 256;
        for (int idx = b * 256 + t; idx < NN * NN; idx += T) {
            const int r = idx >> 9;
            const int c = idx & 511;
            float v;
            if (c > r) {
                v = 0.f;
            } else {
                const int k = (c < r) ? (NN + (r * (r - 1)) / 2 + c) : r;
                float s = __ldg(&bo[k]);
#pragma unroll
                for (int q = 0; q < SPLITK; ++q) s += g_part[q][k];
                v = (c < r) ? s : expf(s);
            }
            g_L[idx] = v;
        }
    }
    grid_barrier(GT);

    // ---- Phase B: GEMM ----
    float (*As)[36] = SAB[0];
    float (*Bs)[36] = SAB[1];

    const int grp  = t >> 6;              // 0..3: k-groups of 16
    const int id64 = t & 63;
    const int tx   = id64 & 7;
    const int ty   = id64 >> 3;

    const int lr = t >> 3;                // 0..31
    const int lc = (t & 7) * 8;           // 0,8,...,56

    float acc[4][4];
#pragma unroll
    for (int i = 0; i < 4; ++i)
#pragma unroll
        for (int j = 0; j < 4; ++j) acc[i][j] = 0.f;

    const int nslab = (bj >> 1) + 1;      // L triangular: k <= bj*32+31

    for (int s = 0; s < nslab; ++s) {
        const int k0 = s * 64;
#pragma unroll
        for (int q = 0; q < 2; ++q) {
            const int c = lc + 4 * q;
            float4 av = *(const float4*)&g_L[(size_t)(bi * 32 + lr) * NN + k0 + c];
            float4 bv = *(const float4*)&g_L[(size_t)(bj * 32 + lr) * NN + k0 + c];
            As[c][lr] = av.x; As[c + 1][lr] = av.y; As[c + 2][lr] = av.z; As[c + 3][lr] = av.w;
            Bs[c][lr] = bv.x; Bs[c + 1][lr] = bv.y; Bs[c + 2][lr] = bv.z; Bs[c + 3][lr] = bv.w;
        }
        __syncthreads();

        const int kb = grp * 16;
#pragma unroll
        for (int kk = 0; kk < 16; ++kk) {
            float4 a  = *(const float4*)&As[kb + kk][ty * 4];
            float4 bb = *(const float4*)&Bs[kb + kk][tx * 4];
            acc[0][0] += a.x * bb.x; acc[0][1] += a.x * bb.y; acc[0][2] += a.x * bb.z; acc[0][3] += a.x * bb.w;
            acc[1][0] += a.y * bb.x; acc[1][1] += a.y * bb.y; acc[1][2] += a.y * bb.z; acc[1][3] += a.y * bb.w;
            acc[2][0] += a.z * bb.x; acc[2][1] += a.z * bb.y; acc[2][2] += a.z * bb.z; acc[2][3] += a.z * bb.w;
            acc[3][0] += a.w * bb.x; acc[3][1] += a.w * bb.y; acc[3][2] += a.w * bb.z; acc[3][3] += a.w * bb.w;
        }
        __syncthreads();
    }

    // combine 4 k-groups: groups 1-3 dump into smem (overlaid), grp 0 sums
    float* red = &SAB[0][0][0];           // 3*64*16 = 3072 floats, fits
    if (grp != 0) {
        float* dst = red + ((grp - 1) * 64 + id64) * 16;
#pragma unroll
        for (int i = 0; i < 4; ++i)
#pragma unroll
            for (int j = 0; j < 4; ++j) dst[i * 4 + j] = acc[i][j];
    }
    __syncthreads();
    if (grp == 0) {
#pragma unroll
        for (int g = 0; g < 3; ++g) {
            const float* src = red + (g * 64 + id64) * 16;
#pragma unroll
            for (int i = 0; i < 4; ++i)
#pragma unroll
                for (int j = 0; j < 4; ++j) acc[i][j] += src[i * 4 + j];
        }

        const int R = bi * 32 + ty * 4;
        const int C = bj * 32 + tx * 4;
#pragma unroll
        for (int i = 0; i < 4; ++i) {
            float4 v; v.x = acc[i][0]; v.y = acc[i][1]; v.z = acc[i][2]; v.w = acc[i][3];
            *(float4*)&D[(size_t)(R + i) * NN + C] = v;
        }
        if (bi != bj) {   // mirror (D symmetric)
#pragma unroll
            for (int j = 0; j < 4; ++j) {
                float4 v; v.x = acc[0][j]; v.y = acc[1][j]; v.z = acc[2][j]; v.w = acc[3][j];
                *(float4*)&D[(size_t)(C + j) * NN + R] = v;
            }
        }
    }
}

// ---------------------------------------------------------------------------
extern "C" void kernel_launch(void* const* d_in, const int* in_sizes, int n_in,
                              void* d_out, int out_size) {
    const float* input = (const float*)d_in[0];
    const float* W0    = (const float*)d_in[1];
    const float* b0    = (const float*)d_in[2];
    const float* W1    = (const float*)d_in[3];
    const float* b1    = (const float*)d_in[4];
    const float* W2    = (const float*)d_in[5];
    const float* b2    = (const float*)d_in[6];
    const float* Wo    = (const float*)d_in[7];
    const float* bo    = (const float*)d_in[8];
    float* out = (float*)d_out;

    // Fused 3-layer MLP + dominant GEMV (single persistent launch)
    mlp_gemv<<<FB, 256>>>(input, W0, b0, W1, b1, W2, b2, Wo);

    // Fused L assembly + D = L L^T
    buildL_gemm<<<GT, 256>>>(bo, out);
}

// round 12
// speedup vs baseline: 1.0580x; 1.0580x over previous
#include <cuda_runtime.h>
#include <math.h>

// Problem constants
#define NN     512
#define HID    1024
#define OUTD   131328          // N + N*(N-1)/2
#define OUT4   (OUTD / 4)      // 32832 float4 columns
#define SPLITK 8
#define JCH    (HID / SPLITK)  // 128 rows of Wo per k-chunk
#define SI     16              // i-splits in fused MLP
#define MB     512             // blocks in fused MLP kernel (32 colgroups x SI)
#define GT     136             // lower-triangle 32x32 tiles (16*17/2)

// Device scratch (no allocation allowed). Referenced ONLY in device code.
__device__ float g_hp[3][SI][HID];       // per-layer split-i partials (pre-bias/tanh)
__device__ float g_part[SPLITK][OUTD];   // split-K partial sums of big GEMV
__device__ float g_L[NN * NN];

// ---------------------------------------------------------------------------
// Software grid barrier (sense-reversal). Safe when all participating blocks
// are co-resident (MB=512 at ~4 CTAs/SM; GT=136 at 1 CTA/SM).
// Generation is monotonic across kernels and graph replays.
// ---------------------------------------------------------------------------
__device__ unsigned g_bar_ctr = 0;
__device__ volatile unsigned g_bar_gen = 0;

__device__ __forceinline__ void grid_barrier(unsigned nblocks) {
    __threadfence();
    __syncthreads();
    if (threadIdx.x == 0) {
        unsigned gen = g_bar_gen;
        if (atomicAdd(&g_bar_ctr, 1) == nblocks - 1) {
            g_bar_ctr = 0;
            __threadfence();
            g_bar_gen = gen + 1;
        } else {
            while (g_bar_gen == gen) __nanosleep(32);
        }
        __threadfence();
    }
    __syncthreads();
}

// ---------------------------------------------------------------------------
// Fused 3-layer MLP (round-10 proven: 12.7us). grid = 512 = 32 colgroups x
// SI=16 i-splits, block = 256. Warp lanes -> 32 consecutive columns.
// ---------------------------------------------------------------------------
template <int IN>
__device__ __forceinline__ void mlp_partial(
    const float* __restrict__ xs, const float* __restrict__ W,
    int cg, int isp, float* __restrict__ outp, float sh[8][32]) {
    const int CHUNK = IN / SI;
    const int CH    = CHUNK / 8;
    const int lane  = threadIdx.x & 31;
    const int w     = threadIdx.x >> 5;
    const int j     = cg * 32 + lane;
    const int base  = isp * CHUNK;
    const int i0    = w * CH;

    float acc = 0.f;
#pragma unroll
    for (int i = 0; i < CH; ++i) {
        acc += xs[i0 + i] * __ldg(&W[(size_t)(base + i0 + i) * 1024 + j]);
    }
    sh[w][lane] = acc;
    __syncthreads();
    if (w == 0) {
        float s = 0.f;
#pragma unroll
        for (int q = 0; q < 8; ++q) s += sh[q][lane];
        outp[j] = s;
    }
    __syncthreads();
}

__global__ void __launch_bounds__(256)
mlp_all(const float* __restrict__ x,
        const float* __restrict__ W0, const float* __restrict__ b0,
        const float* __restrict__ W1, const float* __restrict__ b1,
        const float* __restrict__ W2) {
    __shared__ float sh[8][32];
    __shared__ float xs[HID / SI];

    const int cg  = blockIdx.x & 31;
    const int isp = blockIdx.x >> 5;

    // ---- layer 0: IN=512, raw external input ----
    {
        const int CHUNK = 512 / SI;
        for (int t = threadIdx.x; t < CHUNK; t += 256) xs[t] = x[isp * CHUNK + t];
        __syncthreads();
        mlp_partial<512>(xs, W0, cg, isp, g_hp[0][isp], sh);
    }
    grid_barrier(MB);

    // ---- layer 1: IN=1024 ----
    {
        const int CHUNK = HID / SI;
        for (int t = threadIdx.x; t < CHUNK; t += 256) {
            const int g = isp * CHUNK + t;
            float s = __ldg(&b0[g]);
#pragma unroll
            for (int q = 0; q < SI; ++q) s += g_hp[0][q][g];
            xs[t] = tanhf(s);
        }
        __syncthreads();
        mlp_partial<1024>(xs, W1, cg, isp, g_hp[1][isp], sh);
    }
    grid_barrier(MB);

    // ---- layer 2: IN=1024 ----
    {
        const int CHUNK = HID / SI;
        for (int t = threadIdx.x; t < CHUNK; t += 256) {
            const int g = isp * CHUNK + t;
            float s = __ldg(&b1[g]);
#pragma unroll
            for (int q = 0; q < SI; ++q) s += g_hp[1][q][g];
            xs[t] = tanhf(s);
        }
        __syncthreads();
        mlp_partial<1024>(xs, W2, cg, isp, g_hp[2][isp], sh);
    }
    // final bias+tanh fused into gemv_out's staging
}

// ---------------------------------------------------------------------------
// Big GEMV, split-K (UNCHANGED core, 79.4us / 86% DRAM).
// grid = (129, SPLITK), block = 256.
// ---------------------------------------------------------------------------
__global__ void gemv_out(const float* __restrict__ Wo,
                         const float* __restrict__ b2) {
    const int chunk = blockIdx.y;

    __shared__ float hs[JCH];
    if (threadIdx.x < JCH) {
        const int t = chunk * JCH + threadIdx.x;
        float s = __ldg(&b2[t]);
#pragma unroll
        for (int q = 0; q < SI; ++q) s += g_hp[2][q][t];
        hs[threadIdx.x] = tanhf(s);
    }
    __syncthreads();

    const int k4 = blockIdx.x * blockDim.x + threadIdx.x;
    if (k4 >= OUT4) return;

    const float4* W4 = (const float4*)Wo + (size_t)chunk * JCH * OUT4;
    float ax = 0.f, ay = 0.f, az = 0.f, aw = 0.f;

#pragma unroll 8
    for (int j = 0; j < JCH; ++j) {
        float4 wv = __ldcs(&W4[(size_t)j * OUT4 + k4]);
        float  hj = hs[j];
        ax += hj * wv.x;
        ay += hj * wv.y;
        az += hj * wv.z;
        aw += hj * wv.w;
    }

    float4 r; r.x = ax; r.y = ay; r.z = az; r.w = aw;
    ((float4*)g_part[chunk])[k4] = r;
}

// ---------------------------------------------------------------------------
// Fused build_L + D = L*L^T. grid = GT=136, block = 512 (16 warps/SM).
// Phase A: grid-stride build L. Barrier(GT). Phase B: 32x32 tiles,
// triangular-k, 4x4 microtiles, 8-way k-split, two-stage smem reduction.
// ---------------------------------------------------------------------------
__global__ void __launch_bounds__(512)
buildL_gemm(const float* __restrict__ bo, float* __restrict__ D) {
    __shared__ float SAB[2][64][36];   // As/Bs; reduction buffer overlaid

    const int b = blockIdx.x;
    const int t = threadIdx.x;         // 0..511

    // linear block id -> (bi, bj), bj <= bi
    int bi = (int)((sqrtf(8.f * b + 1.f) - 1.f) * 0.5f);
    while ((bi + 1) * (bi + 2) / 2 <= b) ++bi;
    while (bi * (bi + 1) / 2 > b) --bi;
    const int bj = b - bi * (bi + 1) / 2;

    // ---- Phase A: build L ----
    {
        const int T = GT * 512;
        for (int idx = b * 512 + t; idx < NN * NN; idx += T) {
            const int r = idx >> 9;
            const int c = idx & 511;
            float v;
            if (c > r) {
                v = 0.f;
            } else {
                const int k = (c < r) ? (NN + (r * (r - 1)) / 2 + c) : r;
                float s = __ldg(&bo[k]);
#pragma unroll
                for (int q = 0; q < SPLITK; ++q) s += g_part[q][k];
                v = (c < r) ? s : expf(s);
            }
            g_L[idx] = v;
        }
    }
    grid_barrier(GT);

    // ---- Phase B: GEMM ----
    float (*As)[36] = SAB[0];
    float (*Bs)[36] = SAB[1];

    const int grp  = t >> 6;              // 0..7: k-groups of 8
    const int id64 = t & 63;
    const int tx   = id64 & 7;
    const int ty   = id64 >> 3;

    // slab load: 512 threads, one float4 of A and one of B each
    const int lr = t >> 4;                // 0..31
    const int lc = (t & 15) * 4;          // 0,4,...,60

    float acc[4][4];
#pragma unroll
    for (int i = 0; i < 4; ++i)
#pragma unroll
        for (int j = 0; j < 4; ++j) acc[i][j] = 0.f;

    const int nslab = (bj >> 1) + 1;      // L triangular: k <= bj*32+31

    for (int s = 0; s < nslab; ++s) {
        const int k0 = s * 64;
        float4 av = *(const float4*)&g_L[(size_t)(bi * 32 + lr) * NN + k0 + lc];
        float4 bv = *(const float4*)&g_L[(size_t)(bj * 32 + lr) * NN + k0 + lc];
        As[lc][lr] = av.x; As[lc + 1][lr] = av.y; As[lc + 2][lr] = av.z; As[lc + 3][lr] = av.w;
        Bs[lc][lr] = bv.x; Bs[lc + 1][lr] = bv.y; Bs[lc + 2][lr] = bv.z; Bs[lc + 3][lr] = bv.w;
        __syncthreads();

        const int kb = grp * 8;
#pragma unroll
        for (int kk = 0; kk < 8; ++kk) {
            float4 a  = *(const float4*)&As[kb + kk][ty * 4];
            float4 bb = *(const float4*)&Bs[kb + kk][tx * 4];
            acc[0][0] += a.x * bb.x; acc[0][1] += a.x * bb.y; acc[0][2] += a.x * bb.z; acc[0][3] += a.x * bb.w;
            acc[1][0] += a.y * bb.x; acc[1][1] += a.y * bb.y; acc[1][2] += a.y * bb.z; acc[1][3] += a.y * bb.w;
            acc[2][0] += a.z * bb.x; acc[2][1] += a.z * bb.y; acc[2][2] += a.z * bb.z; acc[2][3] += a.z * bb.w;
            acc[3][0] += a.w * bb.x; acc[3][1] += a.w * bb.y; acc[3][2] += a.w * bb.z; acc[3][3] += a.w * bb.w;
        }
        __syncthreads();
    }

    // two-stage 8-group reduction (overlay on SAB: needs 4*64*16=4096 floats)
    float* red = &SAB[0][0][0];
    if (grp >= 4) {                        // stage 1: groups 4..7 dump
        float* dst = red + ((grp - 4) * 64 + id64) * 16;
#pragma unroll
        for (int i = 0; i < 4; ++i)
#pragma unroll
            for (int j = 0; j < 4; ++j) dst[i * 4 + j] = acc[i][j];
    }
    __syncthreads();
    if (grp < 4) {                         // groups 0..3 absorb partner g+4
        const float* src = red + (grp * 64 + id64) * 16;
#pragma unroll
        for (int i = 0; i < 4; ++i)
#pragma unroll
            for (int j = 0; j < 4; ++j) acc[i][j] += src[i * 4 + j];
    }
    __syncthreads();
    if (grp >= 1 && grp < 4) {             // stage 2: groups 1..3 dump
        float* dst = red + ((grp - 1) * 64 + id64) * 16;
#pragma unroll
        for (int i = 0; i < 4; ++i)
#pragma unroll
            for (int j = 0; j < 4; ++j) dst[i * 4 + j] = acc[i][j];
    }
    __syncthreads();
    if (grp == 0) {
#pragma unroll
        for (int g = 0; g < 3; ++g) {
            const float* src = red + (g * 64 + id64) * 16;
#pragma unroll
            for (int i = 0; i < 4; ++i)
#pragma unroll
                for (int j = 0; j < 4; ++j) acc[i][j] += src[i * 4 + j];
        }

        const int R = bi * 32 + ty * 4;
        const int C = bj * 32 + tx * 4;
#pragma unroll
        for (int i = 0; i < 4; ++i) {
            float4 v; v.x = acc[i][0]; v.y = acc[i][1]; v.z = acc[i][2]; v.w = acc[i][3];
            *(float4*)&D[(size_t)(R + i) * NN + C] = v;
        }
        if (bi != bj) {   // mirror (D symmetric)
#pragma unroll
            for (int j = 0; j < 4; ++j) {
                float4 v; v.x = acc[0][j]; v.y = acc[1][j]; v.z = acc[2][j]; v.w = acc[3][j];
                *(float4*)&D[(size_t)(C + j) * NN + R] = v;
            }
        }
    }
}

// ---------------------------------------------------------------------------
extern "C" void kernel_launch(void* const* d_in, const int* in_sizes, int n_in,
                              void* d_out, int out_size) {
    const float* input = (const float*)d_in[0];
    const float* W0    = (const float*)d_in[1];
    const float* b0    = (const float*)d_in[2];
    const float* W1    = (const float*)d_in[3];
    const float* b1    = (const float*)d_in[4];
    const float* W2    = (const float*)d_in[5];
    const float* b2    = (const float*)d_in[6];
    const float* Wo    = (const float*)d_in[7];
    const float* bo    = (const float*)d_in[8];
    float* out = (float*)d_out;

    // Fused 3-layer MLP (round-10 proven)
    mlp_all<<<MB, 256>>>(input, W0, b0, W1, b1, W2);

    // Dominant GEMV over Wo (537 MB stream)
    dim3 gv((OUT4 + 255) / 256, SPLITK);
    gemv_out<<<gv, 256>>>(Wo, b2);

    // Fused L assembly + D = L L^T (512 threads for latency hiding)
    buildL_gemm<<<GT, 512>>>(bo, out);
}

// round 13
// speedup vs baseline: 1.0836x; 1.0242x over previous
#include <cuda_runtime.h>
#include <math.h>

// Problem constants
#define NN     512
#define HID    1024
#define OUTD   131328          // N + N*(N-1)/2
#define OUT4   (OUTD / 4)      // 32832 float4 columns
#define SPLITK 8
#define JCH    (HID / SPLITK)  // 128 rows of Wo per k-chunk
#define SI     16              // i-splits in fused MLP
#define MB     512             // blocks in fused MLP kernel (32 colgroups x SI)
#define GT     136             // lower-triangle 32x32 tiles (16*17/2)
#define PF     6               // L2-prefetch lines of Wo per MLP thread

// Device scratch (no allocation allowed). Referenced ONLY in device code.
__device__ float g_hp[3][SI][HID];       // per-layer split-i partials (pre-bias/tanh)
__device__ float g_part[SPLITK][OUTD];   // split-K partial sums of big GEMV
__device__ float g_L[NN * NN];

// ---------------------------------------------------------------------------
// Software grid barrier (sense-reversal). Safe when all participating blocks
// are co-resident (MB=512 at ~4 CTAs/SM; GT=136 at 1 CTA/SM).
// ---------------------------------------------------------------------------
__device__ unsigned g_bar_ctr = 0;
__device__ volatile unsigned g_bar_gen = 0;

__device__ __forceinline__ void grid_barrier(unsigned nblocks) {
    __threadfence();
    __syncthreads();
    if (threadIdx.x == 0) {
        unsigned gen = g_bar_gen;
        if (atomicAdd(&g_bar_ctr, 1) == nblocks - 1) {
            g_bar_ctr = 0;
            __threadfence();
            g_bar_gen = gen + 1;
        } else {
            while (g_bar_gen == gen) __nanosleep(32);
        }
        __threadfence();
    }
    __syncthreads();
}

// ---------------------------------------------------------------------------
// Fused 3-layer MLP + L2 pre-stream of Wo's head.
// grid = 512 = 32 colgroups x SI=16 i-splits, block = 256.
// The prefetches use the DRAM bandwidth the MLP leaves ~90% idle, so the
// following 537MB gemv finds its first ~100MB L2-resident.
// ---------------------------------------------------------------------------
template <int IN>
__device__ __forceinline__ void mlp_partial(
    const float* __restrict__ xs, const float* __restrict__ W,
    int cg, int isp, float* __restrict__ outp, float sh[8][32]) {
    const int CHUNK = IN / SI;
    const int CH    = CHUNK / 8;
    const int lane  = threadIdx.x & 31;
    const int w     = threadIdx.x >> 5;
    const int j     = cg * 32 + lane;
    const int base  = isp * CHUNK;
    const int i0    = w * CH;

    float acc = 0.f;
#pragma unroll
    for (int i = 0; i < CH; ++i) {
        acc += xs[i0 + i] * __ldg(&W[(size_t)(base + i0 + i) * 1024 + j]);
    }
    sh[w][lane] = acc;
    __syncthreads();
    if (w == 0) {
        float s = 0.f;
#pragma unroll
        for (int q = 0; q < 8; ++q) s += sh[q][lane];
        outp[j] = s;
    }
    __syncthreads();
}

__global__ void __launch_bounds__(256)
mlp_all(const float* __restrict__ x,
        const float* __restrict__ W0, const float* __restrict__ b0,
        const float* __restrict__ W1, const float* __restrict__ b1,
        const float* __restrict__ W2, const float* __restrict__ Wo) {
    __shared__ float sh[8][32];
    __shared__ float xs[HID / SI];

    const int cg  = blockIdx.x & 31;
    const int isp = blockIdx.x >> 5;

    // Pre-stream head of Wo into L2 (fire-and-forget; rides idle DRAM BW).
    // 512*256 threads * PF lines * 128B = ~100MB, fits in ~126MB L2.
    {
        const size_t tg = (size_t)blockIdx.x * 256 + threadIdx.x;
#pragma unroll
        for (int p = 0; p < PF; ++p) {
            const float* a = Wo + (tg * PF + p) * 32;
            asm volatile("prefetch.global.L2 [%0];" :: "l"(a));
        }
    }

    // ---- layer 0: IN=512, raw external input ----
    {
        const int CHUNK = 512 / SI;
        for (int t = threadIdx.x; t < CHUNK; t += 256) xs[t] = x[isp * CHUNK + t];
        __syncthreads();
        mlp_partial<512>(xs, W0, cg, isp, g_hp[0][isp], sh);
    }
    grid_barrier(MB);

    // ---- layer 1: IN=1024 ----
    {
        const int CHUNK = HID / SI;
        for (int t = threadIdx.x; t < CHUNK; t += 256) {
            const int g = isp * CHUNK + t;
            float s = __ldg(&b0[g]);
#pragma unroll
            for (int q = 0; q < SI; ++q) s += g_hp[0][q][g];
            xs[t] = tanhf(s);
        }
        __syncthreads();
        mlp_partial<1024>(xs, W1, cg, isp, g_hp[1][isp], sh);
    }
    grid_barrier(MB);

    // ---- layer 2: IN=1024 ----
    {
        const int CHUNK = HID / SI;
        for (int t = threadIdx.x; t < CHUNK; t += 256) {
            const int g = isp * CHUNK + t;
            float s = __ldg(&b1[g]);
#pragma unroll
            for (int q = 0; q < SI; ++q) s += g_hp[1][q][g];
            xs[t] = tanhf(s);
        }
        __syncthreads();
        mlp_partial<1024>(xs, W2, cg, isp, g_hp[2][isp], sh);
    }
    // final bias+tanh fused into gemv_out's staging
}

// ---------------------------------------------------------------------------
// Big GEMV, split-K (UNCHANGED core, 79.4us / 86% DRAM; head now L2-hot).
// grid = (129, SPLITK), block = 256.
// ---------------------------------------------------------------------------
__global__ void gemv_out(const float* __restrict__ Wo,
                         const float* __restrict__ b2) {
    const int chunk = blockIdx.y;

    __shared__ float hs[JCH];
    if (threadIdx.x < JCH) {
        const int t = chunk * JCH + threadIdx.x;
        float s = __ldg(&b2[t]);
#pragma unroll
        for (int q = 0; q < SI; ++q) s += g_hp[2][q][t];
        hs[threadIdx.x] = tanhf(s);
    }
    __syncthreads();

    const int k4 = blockIdx.x * blockDim.x + threadIdx.x;
    if (k4 >= OUT4) return;

    const float4* W4 = (const float4*)Wo + (size_t)chunk * JCH * OUT4;
    float ax = 0.f, ay = 0.f, az = 0.f, aw = 0.f;

#pragma unroll 8
    for (int j = 0; j < JCH; ++j) {
        float4 wv = __ldcs(&W4[(size_t)j * OUT4 + k4]);
        float  hj = hs[j];
        ax += hj * wv.x;
        ay += hj * wv.y;
        az += hj * wv.z;
        aw += hj * wv.w;
    }

    float4 r; r.x = ax; r.y = ay; r.z = az; r.w = aw;
    ((float4*)g_part[chunk])[k4] = r;
}

// ---------------------------------------------------------------------------
// Fused build_L + D = L*L^T (round-12 proven, 512 threads).
// ---------------------------------------------------------------------------
__global__ void __launch_bounds__(512)
buildL_gemm(const float* __restrict__ bo, float* __restrict__ D) {
    __shared__ float SAB[2][64][36];   // As/Bs; reduction buffer overlaid

    const int b = blockIdx.x;
    const int t = threadIdx.x;         // 0..511

    // linear block id -> (bi, bj), bj <= bi
    int bi = (int)((sqrtf(8.f * b + 1.f) - 1.f) * 0.5f);
    while ((bi + 1) * (bi + 2) / 2 <= b) ++bi;
    while (bi * (bi + 1) / 2 > b) --bi;
    const int bj = b - bi * (bi + 1) / 2;

    // ---- Phase A: build L ----
    {
        const int T = GT * 512;
        for (int idx = b * 512 + t; idx < NN * NN; idx += T) {
            const int r = idx >> 9;
            const int c = idx & 511;
            float v;
            if (c > r) {
                v = 0.f;
            } else {
                const int k = (c < r) ? (NN + (r * (r - 1)) / 2 + c) : r;
                float s = __ldg(&bo[k]);
#pragma unroll
                for (int q = 0; q < SPLITK; ++q) s += g_part[q][k];
                v = (c < r) ? s : expf(s);
            }
            g_L[idx] = v;
        }
    }
    grid_barrier(GT);

    // ---- Phase B: GEMM ----
    float (*As)[36] = SAB[0];
    float (*Bs)[36] = SAB[1];

    const int grp  = t >> 6;              // 0..7: k-groups of 8
    const int id64 = t & 63;
    const int tx   = id64 & 7;
    const int ty   = id64 >> 3;

    const int lr = t >> 4;                // 0..31
    const int lc = (t & 15) * 4;          // 0,4,...,60

    float acc[4][4];
#pragma unroll
    for (int i = 0; i < 4; ++i)
#pragma unroll
        for (int j = 0; j < 4; ++j) acc[i][j] = 0.f;

    const int nslab = (bj >> 1) + 1;      // L triangular: k <= bj*32+31

    for (int s = 0; s < nslab; ++s) {
        const int k0 = s * 64;
        float4 av = *(const float4*)&g_L[(size_t)(bi * 32 + lr) * NN + k0 + lc];
        float4 bv = *(const float4*)&g_L[(size_t)(bj * 32 + lr) * NN + k0 + lc];
        As[lc][lr] = av.x; As[lc + 1][lr] = av.y; As[lc + 2][lr] = av.z; As[lc + 3][lr] = av.w;
        Bs[lc][lr] = bv.x; Bs[lc + 1][lr] = bv.y; Bs[lc + 2][lr] = bv.z; Bs[lc + 3][lr] = bv.w;
        __syncthreads();

        const int kb = grp * 8;
#pragma unroll
        for (int kk = 0; kk < 8; ++kk) {
            float4 a  = *(const float4*)&As[kb + kk][ty * 4];
            float4 bb = *(const float4*)&Bs[kb + kk][tx * 4];
            acc[0][0] += a.x * bb.x; acc[0][1] += a.x * bb.y; acc[0][2] += a.x * bb.z; acc[0][3] += a.x * bb.w;
            acc[1][0] += a.y * bb.x; acc[1][1] += a.y * bb.y; acc[1][2] += a.y * bb.z; acc[1][3] += a.y * bb.w;
            acc[2][0] += a.z * bb.x; acc[2][1] += a.z * bb.y; acc[2][2] += a.z * bb.z; acc[2][3] += a.z * bb.w;
            acc[3][0] += a.w * bb.x; acc[3][1] += a.w * bb.y; acc[3][2] += a.w * bb.z; acc[3][3] += a.w * bb.w;
        }
        __syncthreads();
    }

    // two-stage 8-group reduction (overlay on SAB)
    float* red = &SAB[0][0][0];
    if (grp >= 4) {
        float* dst = red + ((grp - 4) * 64 + id64) * 16;
#pragma unroll
        for (int i = 0; i < 4; ++i)
#pragma unroll
            for (int j = 0; j < 4; ++j) dst[i * 4 + j] = acc[i][j];
    }
    __syncthreads();
    if (grp < 4) {
        const float* src = red + (grp * 64 + id64) * 16;
#pragma unroll
        for (int i = 0; i < 4; ++i)
#pragma unroll
            for (int j = 0; j < 4; ++j) acc[i][j] += src[i * 4 + j];
    }
    __syncthreads();
    if (grp >= 1 && grp < 4) {
        float* dst = red + ((grp - 1) * 64 + id64) * 16;
#pragma unroll
        for (int i = 0; i < 4; ++i)
#pragma unroll
            for (int j = 0; j < 4; ++j) dst[i * 4 + j] = acc[i][j];
    }
    __syncthreads();
    if (grp == 0) {
#pragma unroll
        for (int g = 0; g < 3; ++g) {
            const float* src = red + (g * 64 + id64) * 16;
#pragma unroll
            for (int i = 0; i < 4; ++i)
#pragma unroll
                for (int j = 0; j < 4; ++j) acc[i][j] += src[i * 4 + j];
        }

        const int R = bi * 32 + ty * 4;
        const int C = bj * 32 + tx * 4;
#pragma unroll
        for (int i = 0; i < 4; ++i) {
            float4 v; v.x = acc[i][0]; v.y = acc[i][1]; v.z = acc[i][2]; v.w = acc[i][3];
            *(float4*)&D[(size_t)(R + i) * NN + C] = v;
        }
        if (bi != bj) {   // mirror (D symmetric)
#pragma unroll
            for (int j = 0; j < 4; ++j) {
                float4 v; v.x = acc[0][j]; v.y = acc[1][j]; v.z = acc[2][j]; v.w = acc[3][j];
                *(float4*)&D[(size_t)(C + j) * NN + R] = v;
            }
        }
    }
}

// ---------------------------------------------------------------------------
extern "C" void kernel_launch(void* const* d_in, const int* in_sizes, int n_in,
                              void* d_out, int out_size) {
    const float* input = (const float*)d_in[0];
    const float* W0    = (const float*)d_in[1];
    const float* b0    = (const float*)d_in[2];
    const float* W1    = (const float*)d_in[3];
    const float* b1    = (const float*)d_in[4];
    const float* W2    = (const float*)d_in[5];
    const float* b2    = (const float*)d_in[6];
    const float* Wo    = (const float*)d_in[7];
    const float* bo    = (const float*)d_in[8];
    float* out = (float*)d_out;

    // Fused 3-layer MLP + L2 pre-stream of Wo's first ~100MB
    mlp_all<<<MB, 256>>>(input, W0, b0, W1, b1, W2, Wo);

    // Dominant GEMV over Wo (537 MB stream; head L2-hot)
    dim3 gv((OUT4 + 255) / 256, SPLITK);
    gemv_out<<<gv, 256>>>(Wo, b2);

    // Fused L assembly + D = L L^T
    buildL_gemm<<<GT, 512>>>(bo, out);
}